// round 1
// baseline (speedup 1.0000x reference)
#include <cuda_runtime.h>

// SparseAudioModel: scatter-add of delayed event signals, inverted to a gather.
//
// Reference:
//   times = indices * 256                        [B, E]
//   out2S[b, t + j] += x[b, e, j]   for all e, j
//   out = out2S[:, :S]
//
// Gather form (no atomics):
//   out[b, s] = sum_e x[b, e, s - time_e]   where time_e <= s
//
// Shapes: B=16, E=64, S=32768. times are multiples of 256, so per-float4
// output group the predicate (time <= s4) is exact for all 4 lanes, and it is
// uniform across the whole block (times broadcast from shared memory).

#define N_SAMPLES 32768
#define N_EVENTS  64
#define STEP_SIZE 256
#define BATCH     16

__global__ __launch_bounds__(256) void sparse_audio_gather(
    const float* __restrict__ x,      // [B, E, S]
    const int*   __restrict__ idx,    // [B, E]
    float*       __restrict__ out)    // [B, S]
{
    __shared__ int s_time[N_EVENTS];

    const int b = blockIdx.y;
    const int t = threadIdx.x;

    if (t < N_EVENTS)
        s_time[t] = idx[b * N_EVENTS + t] * STEP_SIZE;
    __syncthreads();

    // Each thread produces 4 consecutive output samples.
    const int s4 = (blockIdx.x * blockDim.x + t) * 4;

    const float* xb = x + (size_t)b * N_EVENTS * N_SAMPLES;

    float4 acc = make_float4(0.f, 0.f, 0.f, 0.f);

    #pragma unroll 8
    for (int e = 0; e < N_EVENTS; ++e) {
        const int time = s_time[e];           // block-uniform
        if (time <= s4) {                     // uniform branch, no divergence
            const float4 v = *reinterpret_cast<const float4*>(
                xb + (size_t)e * N_SAMPLES + (s4 - time));
            acc.x += v.x; acc.y += v.y; acc.z += v.z; acc.w += v.w;
        }
    }

    *reinterpret_cast<float4*>(out + (size_t)b * N_SAMPLES + s4) = acc;
}

extern "C" void kernel_launch(void* const* d_in, const int* in_sizes, int n_in,
                              void* d_out, int out_size)
{
    const float* x   = (const float*)d_in[0];   // [16, 64, 32768] float32
    const int*   idx = (const int*)  d_in[1];   // [16, 64] int32 (JAX demotes int64)
    float*       out = (float*)d_out;           // [16, 1, 32768] float32

    dim3 block(256);
    dim3 grid(N_SAMPLES / (256 * 4), BATCH);    // (32, 16)
    sparse_audio_gather<<<grid, block>>>(x, idx, out);
}

// round 2
// speedup vs baseline: 1.1007x; 1.1007x over previous
#include <cuda_runtime.h>

// SparseAudioModel: scatter-add of delayed event signals, inverted to a gather.
//
//   out[b, s] = sum_e x[b, e, s - time_e]   where time_e = idx[b,e]*256 <= s
//
// Shapes: B=16, E=64, S=32768. times are multiples of 256, so per-float2
// output group the predicate (time <= s2) is exact for both lanes and uniform
// across the block (times broadcast from shared memory).
//
// R2 change vs R1: float2 per thread instead of float4. Doubles thread count
// (262144 threads, 1024 blocks) to fix grid-limited occupancy (32.7% -> ~60%)
// and shrink the tail wave; traffic unchanged.

#define N_SAMPLES 32768
#define N_EVENTS  64
#define STEP_SIZE 256
#define BATCH     16

__global__ __launch_bounds__(256) void sparse_audio_gather(
    const float* __restrict__ x,      // [B, E, S]
    const int*   __restrict__ idx,    // [B, E]
    float*       __restrict__ out)    // [B, S]
{
    __shared__ int s_time[N_EVENTS];

    const int b = blockIdx.y;
    const int t = threadIdx.x;

    if (t < N_EVENTS)
        s_time[t] = idx[b * N_EVENTS + t] * STEP_SIZE;
    __syncthreads();

    // Each thread produces 2 consecutive output samples.
    const int s2 = (blockIdx.x * blockDim.x + t) * 2;

    const float* xb = x + (size_t)b * N_EVENTS * N_SAMPLES;

    float2 acc = make_float2(0.f, 0.f);

    #pragma unroll 16
    for (int e = 0; e < N_EVENTS; ++e) {
        const int time = s_time[e];           // block-uniform
        if (time <= s2) {                     // uniform branch, no divergence
            const float2 v = *reinterpret_cast<const float2*>(
                xb + (size_t)e * N_SAMPLES + (s2 - time));
            acc.x += v.x;
            acc.y += v.y;
        }
    }

    *reinterpret_cast<float2*>(out + (size_t)b * N_SAMPLES + s2) = acc;
}

extern "C" void kernel_launch(void* const* d_in, const int* in_sizes, int n_in,
                              void* d_out, int out_size)
{
    const float* x   = (const float*)d_in[0];   // [16, 64, 32768] float32
    const int*   idx = (const int*)  d_in[1];   // [16, 64] int32
    float*       out = (float*)d_out;           // [16, 1, 32768] float32

    dim3 block(256);
    dim3 grid(N_SAMPLES / (256 * 2), BATCH);    // (64, 16) = 1024 blocks
    sparse_audio_gather<<<grid, block>>>(x, idx, out);
}